// round 11
// baseline (speedup 1.0000x reference)
#include <cuda_runtime.h>
#include <cuda_bf16.h>
#include <cstdint>

#define NQ   1024
#define DIM  512
#define KQ   65536
#define KD   (KQ * DIM)
#define NCLS 1000
#define TOPK 200
#define SPLITK 1536           /* 3 * DIM bf16-split K: [hi|lo|hi] */
#define BPK  1024             /* B' row width: [hi(512) | lo(512)] */
#define BK   32
#define NCHUNK 48             /* 1536 / 32, divisible by 4 */

// Device scratch (allocation-guard-legal)
__device__ __align__(256) float          g_sim[(size_t)NQ * KQ];     // 256 MB
__device__ __align__(256) __nv_bfloat16  g_bf[(size_t)KQ * BPK];     // 128 MB  [hi|lo]
__device__ __align__(256) __nv_bfloat16  g_af[(size_t)NQ * SPLITK];  //   3 MB  [hi|lo|hi]
__device__ int g_correct;

// ---------------------------------------------------------------------------
// PTX helpers (all base-sm_103 legal: cp.async / ldmatrix / mma.sync)
// ---------------------------------------------------------------------------
__device__ __forceinline__ uint32_t smem_u32(const void* p) {
    uint32_t a;
    asm("{ .reg .u64 t; cvta.to.shared.u64 t, %1; cvt.u32.u64 %0, t; }" : "=r"(a) : "l"(p));
    return a;
}
#define CPASYNC(dst, src) \
    asm volatile("cp.async.cg.shared.global [%0], [%1], 16;" :: "r"(dst), "l"(src))
#define CP_COMMIT()  asm volatile("cp.async.commit_group;" ::: "memory")
#define CP_WAIT2()   asm volatile("cp.async.wait_group 2;" ::: "memory")

#define LDSM_X4(r0, r1, r2, r3, addr) \
    asm volatile("ldmatrix.sync.aligned.m8n8.x4.shared.b16 {%0,%1,%2,%3}, [%4];" \
                 : "=r"(r0), "=r"(r1), "=r"(r2), "=r"(r3) : "r"(addr))

#define MMA16816(c0, c1, c2, c3, a0, a1, a2, a3, b0, b1) \
    asm volatile("mma.sync.aligned.m16n8k16.row.col.f32.bf16.bf16.f32 " \
                 "{%0,%1,%2,%3}, {%4,%5,%6,%7}, {%8,%9}, {%0,%1,%2,%3};" \
                 : "+f"(c0), "+f"(c1), "+f"(c2), "+f"(c3) \
                 : "r"(a0), "r"(a1), "r"(a2), "r"(a3), "r"(b0), "r"(b1))

// ---------------------------------------------------------------------------
// Kernel 0: A-side bf16 hi/lo split
// ---------------------------------------------------------------------------
__global__ void conv_a_kernel(const float* __restrict__ feats)
{
    size_t i4 = (size_t)blockIdx.x * 256 + threadIdx.x;
    float4 v = ((const float4*)feats)[i4];
    int row = (int)(i4 >> 7);
    int c4  = (int)(i4 & 127);
    float f[4] = {v.x, v.y, v.z, v.w};
    __nv_bfloat16 h[4], l[4];
#pragma unroll
    for (int j = 0; j < 4; j++) {
        h[j] = __float2bfloat16(f[j]);
        l[j] = __float2bfloat16(f[j] - __bfloat162float(h[j]));
    }
    __nv_bfloat16* base = g_af + (size_t)row * SPLITK + c4 * 4;
    *(uint2*)base          = *(uint2*)h;   // seg0: A_hi
    *(uint2*)(base + 512)  = *(uint2*)l;   // seg1: A_lo
    *(uint2*)(base + 1024) = *(uint2*)h;   // seg2: A_hi
}

// ---------------------------------------------------------------------------
// Kernel 1 (fused): circular-queue update copy + B-side bf16 split + labels +
// ptr + accumulator reset.
// ---------------------------------------------------------------------------
#define NF4 (KD / 4)

__global__ void copy_conv_b_kernel(const float* __restrict__ feats,
                                   const float* __restrict__ qf,
                                   const int*   __restrict__ labels,
                                   const int*   __restrict__ qlabels,
                                   const int*   __restrict__ qptr,
                                   float*       __restrict__ out)
{
    long long idx = (long long)blockIdx.x * blockDim.x + threadIdx.x;
    const int p = qptr[0];
    if (idx < (long long)NF4) {
        float4 v = ((const float4*)qf)[idx];
        int row = (int)(idx >> 7);
        int c4  = (int)(idx & 127);
        float f[4] = {v.x, v.y, v.z, v.w};
        __nv_bfloat16 h[4], l[4];
#pragma unroll
        for (int j = 0; j < 4; j++) {
            h[j] = __float2bfloat16(f[j]);
            l[j] = __float2bfloat16(f[j] - __bfloat162float(h[j]));
        }
        __nv_bfloat16* bbase = g_bf + (size_t)row * BPK + c4 * 4;
        *(uint2*)bbase         = *(uint2*)h;
        *(uint2*)(bbase + 512) = *(uint2*)l;
        unsigned rel = (unsigned)(row - p);
        float4 vo = (rel < (unsigned)NQ) ? ((const float4*)feats)[rel * 128 + c4] : v;
        float* o = out + 1 + idx * 4;
        o[0] = vo.x; o[1] = vo.y; o[2] = vo.z; o[3] = vo.w;
    } else if (idx < (long long)NF4 + KQ) {
        int i = (int)(idx - NF4);
        unsigned rel = (unsigned)(i - p);
        int v = (rel < (unsigned)NQ) ? labels[rel] : qlabels[i];
        out[1 + (long long)KD + i] = (float)v;
    } else if (idx == (long long)NF4 + KQ) {
        out[1 + (long long)KD + KQ] = (float)((p + NQ) % KQ);
        g_correct = 0;
    }
}

// ---------------------------------------------------------------------------
// Kernel 2: bf16 mma.sync GEMM. CTA tile 128x128, BK=32, 8 warps,
// warp tile 32x64, 4-stage cp.async pipeline (wait_group 2), 2 CTAs/SM.
// ---------------------------------------------------------------------------
#define SA_STAGE 10240                 /* 128*40*2 bytes */
#define SB_STAGE 10240
#define SB_BASE  (4 * SA_STAGE)
#define GEMM_SMEM (4 * SA_STAGE + 4 * SB_STAGE)   /* 81920 */

__global__ __launch_bounds__(256, 2) void gemm_tc_kernel()
{
    extern __shared__ char smem[];
    const uint32_t sbase = smem_u32(smem);
    const int tid  = threadIdx.x;
    const int lane = tid & 31;
    const int wid  = tid >> 5;
    const int wm   = wid & 3;          // 4 warps in M
    const int wn   = wid >> 2;         // 2 warps in N
    const int mBase = blockIdx.x * 128;
    const int nBase = blockIdx.y * 128;

    const uint32_t aAddr0 = sbase +
        (uint32_t)(((wm * 32) + (lane & 15)) * 80 + (lane >> 4) * 16);
    const uint32_t bAddr0 = sbase + SB_BASE +
        (uint32_t)(((wn * 64) + (lane & 7) + ((lane >> 4) & 1) * 8) * 80 + ((lane >> 3) & 1) * 16);

    auto issue_chunk = [&](int c, int s) {
        const int seg  = c >> 4;
        const int aCol = c * BK;
        const int bCol = ((seg == 2) ? 512 : 0) + (c & 15) * BK;
#pragma unroll
        for (int i = 0; i < 2; i++) {
            const int id = tid + i * 256;
            const int r = id >> 2, q = id & 3;
            uint32_t dstA = sbase + s * SA_STAGE + (uint32_t)((r * 40 + q * 8) * 2);
            const void* srcA = g_af + (size_t)(mBase + r) * SPLITK + aCol + q * 8;
            CPASYNC(dstA, srcA);
            uint32_t dstB = sbase + SB_BASE + s * SB_STAGE + (uint32_t)((r * 40 + q * 8) * 2);
            const void* srcB = g_bf + (size_t)(nBase + r) * BPK + bCol + q * 8;
            CPASYNC(dstB, srcB);
        }
    };

    float c_[2][8][4];
#pragma unroll
    for (int i = 0; i < 2; i++)
#pragma unroll
        for (int j = 0; j < 8; j++)
#pragma unroll
            for (int t = 0; t < 4; t++) c_[i][j][t] = 0.f;

    issue_chunk(0, 0); CP_COMMIT();
    issue_chunk(1, 1); CP_COMMIT();
    issue_chunk(2, 2); CP_COMMIT();

    // Iter c: wait until chunk c landed (2 groups may stay pending), barrier
    // (also fences last read of stage (c+3)%4 at iter c-1), issue chunk c+3.
    auto step = [&](int c, int s, int s3) {
        CP_WAIT2();
        __syncthreads();
        if (c + 3 < NCHUNK) issue_chunk(c + 3, s3);
        CP_COMMIT();

        const uint32_t aS = aAddr0 + s * SA_STAGE;
        const uint32_t bS = bAddr0 + s * SB_STAGE;

        uint32_t a[2][2][4], b[2][4][4];
#pragma unroll
        for (int ks = 0; ks < 2; ks++) {
#pragma unroll
            for (int mf = 0; mf < 2; mf++)
                LDSM_X4(a[ks][mf][0], a[ks][mf][1], a[ks][mf][2], a[ks][mf][3],
                        aS + mf * (16 * 80) + ks * 32);
#pragma unroll
            for (int nf2 = 0; nf2 < 4; nf2++)
                LDSM_X4(b[ks][nf2][0], b[ks][nf2][1], b[ks][nf2][2], b[ks][nf2][3],
                        bS + nf2 * (16 * 80) + ks * 32);
        }
#pragma unroll
        for (int ks = 0; ks < 2; ks++)
#pragma unroll
            for (int mf = 0; mf < 2; mf++)
#pragma unroll
                for (int nf2 = 0; nf2 < 4; nf2++) {
                    MMA16816(c_[mf][nf2 * 2][0], c_[mf][nf2 * 2][1],
                             c_[mf][nf2 * 2][2], c_[mf][nf2 * 2][3],
                             a[ks][mf][0], a[ks][mf][1], a[ks][mf][2], a[ks][mf][3],
                             b[ks][nf2][0], b[ks][nf2][1]);
                    MMA16816(c_[mf][nf2 * 2 + 1][0], c_[mf][nf2 * 2 + 1][1],
                             c_[mf][nf2 * 2 + 1][2], c_[mf][nf2 * 2 + 1][3],
                             a[ks][mf][0], a[ks][mf][1], a[ks][mf][2], a[ks][mf][3],
                             b[ks][nf2][2], b[ks][nf2][3]);
                }
    };

#pragma unroll 1
    for (int cc = 0; cc < NCHUNK; cc += 4) {
        step(cc + 0, 0, 3);
        step(cc + 1, 1, 0);
        step(cc + 2, 2, 1);
        step(cc + 3, 3, 2);
    }

    const int rBase = mBase + wm * 32 + (lane >> 2);
    const int cBase = nBase + wn * 64 + (lane & 3) * 2;
#pragma unroll
    for (int mf = 0; mf < 2; mf++) {
#pragma unroll
        for (int nf = 0; nf < 8; nf++) {
            float* p0 = g_sim + (size_t)(rBase + mf * 16) * KQ + cBase + nf * 8;
            float* p1 = p0 + (size_t)8 * KQ;
            *(float2*)p0 = make_float2(c_[mf][nf][0], c_[mf][nf][1]);
            *(float2*)p1 = make_float2(c_[mf][nf][2], c_[mf][nf][3]);
        }
    }
}

// ---------------------------------------------------------------------------
// Kernel 3: per-row top-200 + voting. Occupancy capped to 2 CTAs/SM via dummy
// dynamic smem so concurrent working set (296 rows x 256KB = 76MB) fits L2 ->
// pass 2 reads hit L2 instead of DRAM.
// ---------------------------------------------------------------------------
__device__ __forceinline__ int sim_bin(float v)
{
    int b = (int)((v + 1.0f) * 2048.0f);
    return min(4095, max(0, b));
}

#define CBUF 512
#define KNN_DYN_SMEM 61440

__global__ __launch_bounds__(256) void knn_select_kernel(const int* __restrict__ qlabels,
                                                         const int* __restrict__ labels)
{
    extern __shared__ char dummy_smem[];   // occupancy limiter (unused)
    __shared__ unsigned hist[4096];
    __shared__ unsigned chunk[256];
    __shared__ float    cval[CBUF];
    __shared__ int      cidx[CBUF];
    __shared__ float    score[NCLS];
    __shared__ unsigned s_cnt;
    __shared__ int      s_tbin;

    const int tid = threadIdx.x;
    const int row = blockIdx.x;
    const float4* Sr4 = (const float4*)(g_sim + (size_t)row * KQ);

    for (int b = tid; b < 4096; b += 256) hist[b] = 0;
    for (int i = tid; i < NCLS; i += 256) score[i] = 0.0f;
    if (tid == 0) s_cnt = 0;
    __syncthreads();

    for (int s = 0; s < 64; s++) {
        float4 v = Sr4[tid + s * 256];
        atomicAdd(&hist[sim_bin(v.x)], 1u);
        atomicAdd(&hist[sim_bin(v.y)], 1u);
        atomicAdd(&hist[sim_bin(v.z)], 1u);
        atomicAdd(&hist[sim_bin(v.w)], 1u);
    }
    __syncthreads();

    {
        unsigned cs = 0;
        const int b0 = tid * 16;
#pragma unroll
        for (int b = 0; b < 16; b++) cs += hist[b0 + b];
        chunk[tid] = cs;
    }
    __syncthreads();

    if (tid == 0) {
        unsigned cum = 0;
        int tb = 0;
        for (int t = 255; t >= 0; t--) {
            if (cum + chunk[t] >= (unsigned)TOPK) {
                for (int b = t * 16 + 15;; b--) {
                    if (cum + hist[b] >= (unsigned)TOPK) { tb = b; break; }
                    cum += hist[b];
                }
                break;
            }
            cum += chunk[t];
        }
        s_tbin = tb;
    }
    __syncthreads();
    const int tb = s_tbin;

    for (int s = 0; s < 64; s++) {
        const int base = tid + s * 256;
        float4 v = Sr4[base];
        float vv[4] = {v.x, v.y, v.z, v.w};
#pragma unroll
        for (int c = 0; c < 4; c++) {
            if (sim_bin(vv[c]) >= tb) {
                unsigned pos = atomicAdd(&s_cnt, 1u);
                if (pos < (unsigned)CBUF) { cval[pos] = vv[c]; cidx[pos] = base * 4 + c; }
            }
        }
    }
    __syncthreads();
    const int m = (int)min(s_cnt, (unsigned)CBUF);
    for (int i = tid; i < CBUF; i += 256)
        if (i >= m) { cval[i] = -2.0f; cidx[i] = 0x7FFFFFFF; }
    __syncthreads();

    for (int k = 2; k <= CBUF; k <<= 1) {
        for (int j = k >> 1; j > 0; j >>= 1) {
            for (int t = tid; t < CBUF; t += 256) {
                const int p = t ^ j;
                if (p > t) {
                    float v1 = cval[t], v2 = cval[p];
                    int i1 = cidx[t], i2 = cidx[p];
                    bool firstGreater = (v1 > v2) || (v1 == v2 && i1 < i2);
                    bool up = ((t & k) == 0);
                    if (up != firstGreater) {
                        cval[t] = v2; cval[p] = v1;
                        cidx[t] = i2; cidx[p] = i1;
                    }
                }
            }
            __syncthreads();
        }
    }

    if (tid < TOPK) {
        float w = expf(cval[tid] * (1.0f / 0.07f));
        atomicAdd(&score[qlabels[cidx[tid]]], w);
    }
    __syncthreads();

    float best = -1.0f;
    int bc = 0;
#pragma unroll
    for (int rep = 0; rep < 4; rep++) {
        const int c = tid + rep * 256;
        if (c < NCLS) {
            float sc = score[c];
            if (sc > best) { best = sc; bc = c; }
        }
    }
    __syncthreads();
    cval[tid] = best; cidx[tid] = bc;
    __syncthreads();
    for (int off = 128; off > 0; off >>= 1) {
        if (tid < off) {
            float v2 = cval[tid + off]; int c2 = cidx[tid + off];
            if (v2 > cval[tid] || (v2 == cval[tid] && c2 < cidx[tid])) {
                cval[tid] = v2; cidx[tid] = c2;
            }
        }
        __syncthreads();
    }
    if (tid == 0 && cidx[0] == labels[row]) atomicAdd(&g_correct, 1);
}

__global__ void finalize_kernel(float* __restrict__ out)
{
    out[0] = (float)g_correct * (1.0f / 1024.0f);
}

// ---------------------------------------------------------------------------
extern "C" void kernel_launch(void* const* d_in, const int* in_sizes, int n_in,
                              void* d_out, int out_size)
{
    const float* feats   = (const float*)d_in[0];
    const float* qf      = (const float*)d_in[1];
    const int*   labels  = (const int*)d_in[2];
    const int*   qlabels = (const int*)d_in[3];
    const int*   qptr    = (const int*)d_in[4];
    float* out = (float*)d_out;

    cudaFuncSetAttribute(gemm_tc_kernel, cudaFuncAttributeMaxDynamicSharedMemorySize, GEMM_SMEM);
    cudaFuncSetAttribute(knn_select_kernel, cudaFuncAttributeMaxDynamicSharedMemorySize, KNN_DYN_SMEM);

    conv_a_kernel<<<(NQ * DIM / 4) / 256, 256>>>(feats);

    const long long total = (long long)NF4 + KQ + 1;
    copy_conv_b_kernel<<<(int)((total + 255) / 256), 256>>>(feats, qf, labels, qlabels, qptr, out);

    gemm_tc_kernel<<<dim3(8, 512), 256, GEMM_SMEM>>>();
    knn_select_kernel<<<NQ, 256, KNN_DYN_SMEM>>>(qlabels, labels);
    finalize_kernel<<<1, 1>>>(out);
}

// round 12
// speedup vs baseline: 1.0946x; 1.0946x over previous
#include <cuda_runtime.h>
#include <cuda_bf16.h>
#include <cstdint>

#define NQ   1024
#define DIM  512
#define KQ   65536
#define KD   (KQ * DIM)
#define NCLS 1000
#define TOPK 200
#define SPLITK 1536           /* 3 * DIM bf16-split K: [hi|lo|hi] */
#define BPK  1024             /* B' row width: [hi(512) | lo(512)] */
#define BK   32
#define NCHUNK 48             /* 1536 / 32, divisible by 4 */

// Device scratch (allocation-guard-legal)
__device__ __align__(256) float          g_sim[(size_t)NQ * KQ];     // 256 MB
__device__ __align__(256) __nv_bfloat16  g_bf[(size_t)KQ * BPK];     // 128 MB  [hi|lo]
__device__ __align__(256) __nv_bfloat16  g_af[(size_t)NQ * SPLITK];  //   3 MB  [hi|lo|hi]
__device__ int g_correct;

// ---------------------------------------------------------------------------
// PTX helpers (all base-sm_103 legal: cp.async / ldmatrix / mma.sync)
// ---------------------------------------------------------------------------
__device__ __forceinline__ uint32_t smem_u32(const void* p) {
    uint32_t a;
    asm("{ .reg .u64 t; cvta.to.shared.u64 t, %1; cvt.u32.u64 %0, t; }" : "=r"(a) : "l"(p));
    return a;
}
#define CPASYNC(dst, src) \
    asm volatile("cp.async.cg.shared.global [%0], [%1], 16;" :: "r"(dst), "l"(src))
#define CP_COMMIT()  asm volatile("cp.async.commit_group;" ::: "memory")
#define CP_WAIT2()   asm volatile("cp.async.wait_group 2;" ::: "memory")

#define LDSM_X4(r0, r1, r2, r3, addr) \
    asm volatile("ldmatrix.sync.aligned.m8n8.x4.shared.b16 {%0,%1,%2,%3}, [%4];" \
                 : "=r"(r0), "=r"(r1), "=r"(r2), "=r"(r3) : "r"(addr))

#define MMA16816(c0, c1, c2, c3, a0, a1, a2, a3, b0, b1) \
    asm volatile("mma.sync.aligned.m16n8k16.row.col.f32.bf16.bf16.f32 " \
                 "{%0,%1,%2,%3}, {%4,%5,%6,%7}, {%8,%9}, {%0,%1,%2,%3};" \
                 : "+f"(c0), "+f"(c1), "+f"(c2), "+f"(c3) \
                 : "r"(a0), "r"(a1), "r"(a2), "r"(a3), "r"(b0), "r"(b1))

// ---------------------------------------------------------------------------
// Kernel 0: A-side bf16 hi/lo split
// ---------------------------------------------------------------------------
__global__ void conv_a_kernel(const float* __restrict__ feats)
{
    size_t i4 = (size_t)blockIdx.x * 256 + threadIdx.x;
    float4 v = ((const float4*)feats)[i4];
    int row = (int)(i4 >> 7);
    int c4  = (int)(i4 & 127);
    float f[4] = {v.x, v.y, v.z, v.w};
    __nv_bfloat16 h[4], l[4];
#pragma unroll
    for (int j = 0; j < 4; j++) {
        h[j] = __float2bfloat16(f[j]);
        l[j] = __float2bfloat16(f[j] - __bfloat162float(h[j]));
    }
    __nv_bfloat16* base = g_af + (size_t)row * SPLITK + c4 * 4;
    *(uint2*)base          = *(uint2*)h;   // seg0: A_hi
    *(uint2*)(base + 512)  = *(uint2*)l;   // seg1: A_lo
    *(uint2*)(base + 1024) = *(uint2*)h;   // seg2: A_hi
}

// ---------------------------------------------------------------------------
// Kernel 1 (fused): circular-queue update copy + B-side bf16 split + labels +
// ptr + accumulator reset.
// ---------------------------------------------------------------------------
#define NF4 (KD / 4)

__global__ void copy_conv_b_kernel(const float* __restrict__ feats,
                                   const float* __restrict__ qf,
                                   const int*   __restrict__ labels,
                                   const int*   __restrict__ qlabels,
                                   const int*   __restrict__ qptr,
                                   float*       __restrict__ out)
{
    long long idx = (long long)blockIdx.x * blockDim.x + threadIdx.x;
    const int p = qptr[0];
    if (idx < (long long)NF4) {
        float4 v = ((const float4*)qf)[idx];
        int row = (int)(idx >> 7);
        int c4  = (int)(idx & 127);
        float f[4] = {v.x, v.y, v.z, v.w};
        __nv_bfloat16 h[4], l[4];
#pragma unroll
        for (int j = 0; j < 4; j++) {
            h[j] = __float2bfloat16(f[j]);
            l[j] = __float2bfloat16(f[j] - __bfloat162float(h[j]));
        }
        __nv_bfloat16* bbase = g_bf + (size_t)row * BPK + c4 * 4;
        *(uint2*)bbase         = *(uint2*)h;
        *(uint2*)(bbase + 512) = *(uint2*)l;
        unsigned rel = (unsigned)(row - p);
        float4 vo = (rel < (unsigned)NQ) ? ((const float4*)feats)[rel * 128 + c4] : v;
        float* o = out + 1 + idx * 4;
        o[0] = vo.x; o[1] = vo.y; o[2] = vo.z; o[3] = vo.w;
    } else if (idx < (long long)NF4 + KQ) {
        int i = (int)(idx - NF4);
        unsigned rel = (unsigned)(i - p);
        int v = (rel < (unsigned)NQ) ? labels[rel] : qlabels[i];
        out[1 + (long long)KD + i] = (float)v;
    } else if (idx == (long long)NF4 + KQ) {
        out[1 + (long long)KD + KQ] = (float)((p + NQ) % KQ);
        g_correct = 0;
    }
}

// ---------------------------------------------------------------------------
// Kernel 2: bf16 mma.sync GEMM. CTA tile 128x128, BK=32, 8 warps,
// warp tile 32x64, 4-stage cp.async pipeline (wait_group 2), 2 CTAs/SM.
// ---------------------------------------------------------------------------
#define SA_STAGE 10240                 /* 128*40*2 bytes */
#define SB_STAGE 10240
#define SB_BASE  (4 * SA_STAGE)
#define GEMM_SMEM (4 * SA_STAGE + 4 * SB_STAGE)   /* 81920 */

__global__ __launch_bounds__(256, 2) void gemm_tc_kernel()
{
    extern __shared__ char smem[];
    const uint32_t sbase = smem_u32(smem);
    const int tid  = threadIdx.x;
    const int lane = tid & 31;
    const int wid  = tid >> 5;
    const int wm   = wid & 3;          // 4 warps in M
    const int wn   = wid >> 2;         // 2 warps in N
    const int mBase = blockIdx.x * 128;
    const int nBase = blockIdx.y * 128;

    const uint32_t aAddr0 = sbase +
        (uint32_t)(((wm * 32) + (lane & 15)) * 80 + (lane >> 4) * 16);
    const uint32_t bAddr0 = sbase + SB_BASE +
        (uint32_t)(((wn * 64) + (lane & 7) + ((lane >> 4) & 1) * 8) * 80 + ((lane >> 3) & 1) * 16);

    auto issue_chunk = [&](int c, int s) {
        const int seg  = c >> 4;
        const int aCol = c * BK;
        const int bCol = ((seg == 2) ? 512 : 0) + (c & 15) * BK;
#pragma unroll
        for (int i = 0; i < 2; i++) {
            const int id = tid + i * 256;
            const int r = id >> 2, q = id & 3;
            uint32_t dstA = sbase + s * SA_STAGE + (uint32_t)((r * 40 + q * 8) * 2);
            const void* srcA = g_af + (size_t)(mBase + r) * SPLITK + aCol + q * 8;
            CPASYNC(dstA, srcA);
            uint32_t dstB = sbase + SB_BASE + s * SB_STAGE + (uint32_t)((r * 40 + q * 8) * 2);
            const void* srcB = g_bf + (size_t)(nBase + r) * BPK + bCol + q * 8;
            CPASYNC(dstB, srcB);
        }
    };

    float c_[2][8][4];
#pragma unroll
    for (int i = 0; i < 2; i++)
#pragma unroll
        for (int j = 0; j < 8; j++)
#pragma unroll
            for (int t = 0; t < 4; t++) c_[i][j][t] = 0.f;

    issue_chunk(0, 0); CP_COMMIT();
    issue_chunk(1, 1); CP_COMMIT();
    issue_chunk(2, 2); CP_COMMIT();

    auto step = [&](int c, int s, int s3) {
        CP_WAIT2();
        __syncthreads();
        if (c + 3 < NCHUNK) issue_chunk(c + 3, s3);
        CP_COMMIT();

        const uint32_t aS = aAddr0 + s * SA_STAGE;
        const uint32_t bS = bAddr0 + s * SB_STAGE;

        uint32_t a[2][2][4], b[2][4][4];
#pragma unroll
        for (int ks = 0; ks < 2; ks++) {
#pragma unroll
            for (int mf = 0; mf < 2; mf++)
                LDSM_X4(a[ks][mf][0], a[ks][mf][1], a[ks][mf][2], a[ks][mf][3],
                        aS + mf * (16 * 80) + ks * 32);
#pragma unroll
            for (int nf2 = 0; nf2 < 4; nf2++)
                LDSM_X4(b[ks][nf2][0], b[ks][nf2][1], b[ks][nf2][2], b[ks][nf2][3],
                        bS + nf2 * (16 * 80) + ks * 32);
        }
#pragma unroll
        for (int ks = 0; ks < 2; ks++)
#pragma unroll
            for (int mf = 0; mf < 2; mf++)
#pragma unroll
                for (int nf2 = 0; nf2 < 4; nf2++) {
                    MMA16816(c_[mf][nf2 * 2][0], c_[mf][nf2 * 2][1],
                             c_[mf][nf2 * 2][2], c_[mf][nf2 * 2][3],
                             a[ks][mf][0], a[ks][mf][1], a[ks][mf][2], a[ks][mf][3],
                             b[ks][nf2][0], b[ks][nf2][1]);
                    MMA16816(c_[mf][nf2 * 2 + 1][0], c_[mf][nf2 * 2 + 1][1],
                             c_[mf][nf2 * 2 + 1][2], c_[mf][nf2 * 2 + 1][3],
                             a[ks][mf][0], a[ks][mf][1], a[ks][mf][2], a[ks][mf][3],
                             b[ks][nf2][2], b[ks][nf2][3]);
                }
    };

#pragma unroll 1
    for (int cc = 0; cc < NCHUNK; cc += 4) {
        step(cc + 0, 0, 3);
        step(cc + 1, 1, 0);
        step(cc + 2, 2, 1);
        step(cc + 3, 3, 2);
    }

    const int rBase = mBase + wm * 32 + (lane >> 2);
    const int cBase = nBase + wn * 64 + (lane & 3) * 2;
#pragma unroll
    for (int mf = 0; mf < 2; mf++) {
#pragma unroll
        for (int nf = 0; nf < 8; nf++) {
            float* p0 = g_sim + (size_t)(rBase + mf * 16) * KQ + cBase + nf * 8;
            float* p1 = p0 + (size_t)8 * KQ;
            *(float2*)p0 = make_float2(c_[mf][nf][0], c_[mf][nf][1]);
            *(float2*)p1 = make_float2(c_[mf][nf][2], c_[mf][nf][3]);
        }
    }
}

// ---------------------------------------------------------------------------
// Kernel 3: per-row top-200 + voting.
// Fast path: ONE pass over sim gathering values > THRESH (statistically
// 500..730 candidates for unit-vector dot products, always a superset of the
// top-200). Exact inline fallback (histogram threshold + regather) if a row's
// count falls outside [TOPK, CBUF] — exact on ANY input.
// Full occupancy (no cap): pass is bandwidth-bound and needs the parallelism.
// ---------------------------------------------------------------------------
__device__ __forceinline__ int sim_bin(float v)
{
    int b = (int)((v + 1.0f) * 2048.0f);
    return min(4095, max(0, b));
}

#define CBUF 1024
#define THRESH 0.104f

__global__ __launch_bounds__(256) void knn_select_kernel(const int* __restrict__ qlabels,
                                                         const int* __restrict__ labels)
{
    __shared__ unsigned hist[4096];       // fallback only
    __shared__ float    cval[CBUF];
    __shared__ int      cidx[CBUF];
    __shared__ float    score[NCLS];
    __shared__ unsigned s_cnt;
    __shared__ int      s_tbin;

    const int tid = threadIdx.x;
    const int row = blockIdx.x;
    const float4* Sr4 = (const float4*)(g_sim + (size_t)row * KQ);

    for (int i = tid; i < NCLS; i += 256) score[i] = 0.0f;
    if (tid == 0) s_cnt = 0;
    __syncthreads();

    // ---- Fast path: single-pass gather above static threshold ----
    for (int s = 0; s < 64; s++) {
        const int base = tid + s * 256;
        float4 v = Sr4[base];
        float vv[4] = {v.x, v.y, v.z, v.w};
#pragma unroll
        for (int c = 0; c < 4; c++) {
            if (vv[c] > THRESH) {
                unsigned pos = atomicAdd(&s_cnt, 1u);
                if (pos < (unsigned)CBUF) { cval[pos] = vv[c]; cidx[pos] = base * 4 + c; }
            }
        }
    }
    __syncthreads();

    // ---- Exact fallback (never triggers on this distribution) ----
    if (s_cnt < (unsigned)TOPK || s_cnt > (unsigned)CBUF) {
        for (int b = tid; b < 4096; b += 256) hist[b] = 0;
        __syncthreads();
        for (int s = 0; s < 64; s++) {
            float4 v = Sr4[tid + s * 256];
            atomicAdd(&hist[sim_bin(v.x)], 1u);
            atomicAdd(&hist[sim_bin(v.y)], 1u);
            atomicAdd(&hist[sim_bin(v.z)], 1u);
            atomicAdd(&hist[sim_bin(v.w)], 1u);
        }
        __syncthreads();
        if (tid == 0) {
            unsigned cum = 0;
            int tb = 0;
            for (int b = 4095; b >= 0; b--) {
                if (cum + hist[b] >= (unsigned)TOPK) { tb = b; break; }
                cum += hist[b];
            }
            s_tbin = tb;
            s_cnt = 0;
        }
        __syncthreads();
        const int tb = s_tbin;
        for (int s = 0; s < 64; s++) {
            const int base = tid + s * 256;
            float4 v = Sr4[base];
            float vv[4] = {v.x, v.y, v.z, v.w};
#pragma unroll
            for (int c = 0; c < 4; c++) {
                if (sim_bin(vv[c]) >= tb) {
                    unsigned pos = atomicAdd(&s_cnt, 1u);
                    if (pos < (unsigned)CBUF) { cval[pos] = vv[c]; cidx[pos] = base * 4 + c; }
                }
            }
        }
        __syncthreads();
    }

    const int m = (int)min(s_cnt, (unsigned)CBUF);
    for (int i = tid; i < CBUF; i += 256)
        if (i >= m) { cval[i] = -2.0f; cidx[i] = 0x7FFFFFFF; }
    __syncthreads();

    // Bitonic sort 1024: descending by value, ascending by index on ties
    for (int k = 2; k <= CBUF; k <<= 1) {
        for (int j = k >> 1; j > 0; j >>= 1) {
            for (int t = tid; t < CBUF; t += 256) {
                const int p = t ^ j;
                if (p > t) {
                    float v1 = cval[t], v2 = cval[p];
                    int i1 = cidx[t], i2 = cidx[p];
                    bool firstGreater = (v1 > v2) || (v1 == v2 && i1 < i2);
                    bool up = ((t & k) == 0);
                    if (up != firstGreater) {
                        cval[t] = v2; cval[p] = v1;
                        cidx[t] = i2; cidx[p] = i1;
                    }
                }
            }
            __syncthreads();
        }
    }

    // Vote: exact top-200 weights scattered into per-class scores
    if (tid < TOPK) {
        float w = expf(cval[tid] * (1.0f / 0.07f));
        atomicAdd(&score[qlabels[cidx[tid]]], w);
    }
    __syncthreads();

    // Argmax over classes (lowest class index on ties)
    float best = -1.0f;
    int bc = 0;
#pragma unroll
    for (int rep = 0; rep < 4; rep++) {
        const int c = tid + rep * 256;
        if (c < NCLS) {
            float sc = score[c];
            if (sc > best) { best = sc; bc = c; }
        }
    }
    __syncthreads();
    cval[tid] = best; cidx[tid] = bc;
    __syncthreads();
    for (int off = 128; off > 0; off >>= 1) {
        if (tid < off) {
            float v2 = cval[tid + off]; int c2 = cidx[tid + off];
            if (v2 > cval[tid] || (v2 == cval[tid] && c2 < cidx[tid])) {
                cval[tid] = v2; cidx[tid] = c2;
            }
        }
        __syncthreads();
    }
    if (tid == 0 && cidx[0] == labels[row]) atomicAdd(&g_correct, 1);
}

__global__ void finalize_kernel(float* __restrict__ out)
{
    out[0] = (float)g_correct * (1.0f / 1024.0f);
}

// ---------------------------------------------------------------------------
extern "C" void kernel_launch(void* const* d_in, const int* in_sizes, int n_in,
                              void* d_out, int out_size)
{
    const float* feats   = (const float*)d_in[0];
    const float* qf      = (const float*)d_in[1];
    const int*   labels  = (const int*)d_in[2];
    const int*   qlabels = (const int*)d_in[3];
    const int*   qptr    = (const int*)d_in[4];
    float* out = (float*)d_out;

    cudaFuncSetAttribute(gemm_tc_kernel, cudaFuncAttributeMaxDynamicSharedMemorySize, GEMM_SMEM);

    conv_a_kernel<<<(NQ * DIM / 4) / 256, 256>>>(feats);

    const long long total = (long long)NF4 + KQ + 1;
    copy_conv_b_kernel<<<(int)((total + 255) / 256), 256>>>(feats, qf, labels, qlabels, qptr, out);

    gemm_tc_kernel<<<dim3(8, 512), 256, GEMM_SMEM>>>();
    knn_select_kernel<<<NQ, 256>>>(qlabels, labels);
    finalize_kernel<<<1, 1>>>(out);
}

// round 16
// speedup vs baseline: 1.1592x; 1.0590x over previous
#include <cuda_runtime.h>
#include <cuda_bf16.h>
#include <cstdint>

#define NQ   1024
#define DIM  512
#define KQ   65536
#define KD   (KQ * DIM)
#define NCLS 1000
#define TOPK 200
#define SPLITK 1536           /* 3 * DIM bf16-split K: [hi|lo|hi] */
#define BPK  1024             /* B' row width: [hi(512) | lo(512)] */
#define BK   32
#define NCHUNK 48             /* 1536 / 32, divisible by 4 */
#define CCAP 1024             /* per-row candidate capacity */
#define THRESH 0.104f

// Device scratch (allocation-guard-legal)
__device__ __align__(256) __nv_bfloat16  g_bf[(size_t)KQ * BPK];       // 128 MB [hi|lo]
__device__ __align__(256) __nv_bfloat16  g_af[(size_t)NQ * SPLITK];    //   3 MB [hi|lo|hi]
__device__ __align__(256) float          g_cval[(size_t)NQ * CCAP];    //   4 MB
__device__ __align__(256) int            g_cidx[(size_t)NQ * CCAP];    //   4 MB
__device__ int g_ccnt[NQ];
__device__ int g_correct;

// ---------------------------------------------------------------------------
// PTX helpers (all base-sm_103 legal: cp.async / ldmatrix / mma.sync)
// ---------------------------------------------------------------------------
__device__ __forceinline__ uint32_t smem_u32(const void* p) {
    uint32_t a;
    asm("{ .reg .u64 t; cvta.to.shared.u64 t, %1; cvt.u32.u64 %0, t; }" : "=r"(a) : "l"(p));
    return a;
}
#define CPASYNC(dst, src) \
    asm volatile("cp.async.cg.shared.global [%0], [%1], 16;" :: "r"(dst), "l"(src))
#define CP_COMMIT()  asm volatile("cp.async.commit_group;" ::: "memory")
#define CP_WAIT2()   asm volatile("cp.async.wait_group 2;" ::: "memory")

#define LDSM_X4(r0, r1, r2, r3, addr) \
    asm volatile("ldmatrix.sync.aligned.m8n8.x4.shared.b16 {%0,%1,%2,%3}, [%4];" \
                 : "=r"(r0), "=r"(r1), "=r"(r2), "=r"(r3) : "r"(addr))

#define MMA16816(c0, c1, c2, c3, a0, a1, a2, a3, b0, b1) \
    asm volatile("mma.sync.aligned.m16n8k16.row.col.f32.bf16.bf16.f32 " \
                 "{%0,%1,%2,%3}, {%4,%5,%6,%7}, {%8,%9}, {%0,%1,%2,%3};" \
                 : "+f"(c0), "+f"(c1), "+f"(c2), "+f"(c3) \
                 : "r"(a0), "r"(a1), "r"(a2), "r"(a3), "r"(b0), "r"(b1))

// ---------------------------------------------------------------------------
// Kernel 0: A-side bf16 hi/lo split + candidate-counter reset
// ---------------------------------------------------------------------------
__global__ void conv_a_kernel(const float* __restrict__ feats)
{
    if (blockIdx.x == 0) {
        for (int i = threadIdx.x; i < NQ; i += 256) g_ccnt[i] = 0;
    }
    size_t i4 = (size_t)blockIdx.x * 256 + threadIdx.x;
    float4 v = ((const float4*)feats)[i4];
    int row = (int)(i4 >> 7);
    int c4  = (int)(i4 & 127);
    float f[4] = {v.x, v.y, v.z, v.w};
    __nv_bfloat16 h[4], l[4];
#pragma unroll
    for (int j = 0; j < 4; j++) {
        h[j] = __float2bfloat16(f[j]);
        l[j] = __float2bfloat16(f[j] - __bfloat162float(h[j]));
    }
    __nv_bfloat16* base = g_af + (size_t)row * SPLITK + c4 * 4;
    *(uint2*)base          = *(uint2*)h;   // seg0: A_hi
    *(uint2*)(base + 512)  = *(uint2*)l;   // seg1: A_lo
    *(uint2*)(base + 1024) = *(uint2*)h;   // seg2: A_hi
}

// ---------------------------------------------------------------------------
// Kernel 1 (fused): circular-queue update copy + B-side bf16 split + labels +
// ptr + accumulator reset.
// ---------------------------------------------------------------------------
#define NF4 (KD / 4)

__global__ void copy_conv_b_kernel(const float* __restrict__ feats,
                                   const float* __restrict__ qf,
                                   const int*   __restrict__ labels,
                                   const int*   __restrict__ qlabels,
                                   const int*   __restrict__ qptr,
                                   float*       __restrict__ out)
{
    long long idx = (long long)blockIdx.x * blockDim.x + threadIdx.x;
    const int p = qptr[0];
    if (idx < (long long)NF4) {
        float4 v = ((const float4*)qf)[idx];
        int row = (int)(idx >> 7);
        int c4  = (int)(idx & 127);
        float f[4] = {v.x, v.y, v.z, v.w};
        __nv_bfloat16 h[4], l[4];
#pragma unroll
        for (int j = 0; j < 4; j++) {
            h[j] = __float2bfloat16(f[j]);
            l[j] = __float2bfloat16(f[j] - __bfloat162float(h[j]));
        }
        __nv_bfloat16* bbase = g_bf + (size_t)row * BPK + c4 * 4;
        *(uint2*)bbase         = *(uint2*)h;
        *(uint2*)(bbase + 512) = *(uint2*)l;
        unsigned rel = (unsigned)(row - p);
        float4 vo = (rel < (unsigned)NQ) ? ((const float4*)feats)[rel * 128 + c4] : v;
        float* o = out + 1 + idx * 4;
        o[0] = vo.x; o[1] = vo.y; o[2] = vo.z; o[3] = vo.w;
    } else if (idx < (long long)NF4 + KQ) {
        int i = (int)(idx - NF4);
        unsigned rel = (unsigned)(i - p);
        int v = (rel < (unsigned)NQ) ? labels[rel] : qlabels[i];
        out[1 + (long long)KD + i] = (float)v;
    } else if (idx == (long long)NF4 + KQ) {
        out[1 + (long long)KD + KQ] = (float)((p + NQ) % KQ);
        g_correct = 0;
    }
}

// ---------------------------------------------------------------------------
// Kernel 2: bf16 mma.sync GEMM. CTA tile 128x128, BK=32, 8 warps,
// warp tile 32x64, 4-stage cp.async pipeline (wait_group 2), 2 CTAs/SM.
// Epilogue: NO sim store — inline threshold filter appends (val, idx) to
// per-row candidate lists (saves 256 MB store + 256 MB later read).
// ---------------------------------------------------------------------------
#define SA_STAGE 10240                 /* 128*40*2 bytes */
#define SB_STAGE 10240
#define SB_BASE  (4 * SA_STAGE)
#define GEMM_SMEM (4 * SA_STAGE + 4 * SB_STAGE)   /* 81920 */

__device__ __forceinline__ void cand_append(int row, int col, float v)
{
    if (v > THRESH) {
        int pos = atomicAdd(&g_ccnt[row], 1);
        if (pos < CCAP) {
            g_cval[(size_t)row * CCAP + pos] = v;
            g_cidx[(size_t)row * CCAP + pos] = col;
        }
    }
}

__global__ __launch_bounds__(256, 2) void gemm_tc_kernel()
{
    extern __shared__ char smem[];
    const uint32_t sbase = smem_u32(smem);
    const int tid  = threadIdx.x;
    const int lane = tid & 31;
    const int wid  = tid >> 5;
    const int wm   = wid & 3;          // 4 warps in M
    const int wn   = wid >> 2;         // 2 warps in N
    const int mBase = blockIdx.x * 128;
    const int nBase = blockIdx.y * 128;

    const uint32_t aAddr0 = sbase +
        (uint32_t)(((wm * 32) + (lane & 15)) * 80 + (lane >> 4) * 16);
    const uint32_t bAddr0 = sbase + SB_BASE +
        (uint32_t)(((wn * 64) + (lane & 7) + ((lane >> 4) & 1) * 8) * 80 + ((lane >> 3) & 1) * 16);

    auto issue_chunk = [&](int c, int s) {
        const int seg  = c >> 4;
        const int aCol = c * BK;
        const int bCol = ((seg == 2) ? 512 : 0) + (c & 15) * BK;
#pragma unroll
        for (int i = 0; i < 2; i++) {
            const int id = tid + i * 256;
            const int r = id >> 2, q = id & 3;
            uint32_t dstA = sbase + s * SA_STAGE + (uint32_t)((r * 40 + q * 8) * 2);
            const void* srcA = g_af + (size_t)(mBase + r) * SPLITK + aCol + q * 8;
            CPASYNC(dstA, srcA);
            uint32_t dstB = sbase + SB_BASE + s * SB_STAGE + (uint32_t)((r * 40 + q * 8) * 2);
            const void* srcB = g_bf + (size_t)(nBase + r) * BPK + bCol + q * 8;
            CPASYNC(dstB, srcB);
        }
    };

    float c_[2][8][4];
#pragma unroll
    for (int i = 0; i < 2; i++)
#pragma unroll
        for (int j = 0; j < 8; j++)
#pragma unroll
            for (int t = 0; t < 4; t++) c_[i][j][t] = 0.f;

    issue_chunk(0, 0); CP_COMMIT();
    issue_chunk(1, 1); CP_COMMIT();
    issue_chunk(2, 2); CP_COMMIT();

    auto step = [&](int c, int s, int s3) {
        CP_WAIT2();
        __syncthreads();
        if (c + 3 < NCHUNK) issue_chunk(c + 3, s3);
        CP_COMMIT();

        const uint32_t aS = aAddr0 + s * SA_STAGE;
        const uint32_t bS = bAddr0 + s * SB_STAGE;

        uint32_t a[2][2][4], b[2][4][4];
#pragma unroll
        for (int ks = 0; ks < 2; ks++) {
#pragma unroll
            for (int mf = 0; mf < 2; mf++)
                LDSM_X4(a[ks][mf][0], a[ks][mf][1], a[ks][mf][2], a[ks][mf][3],
                        aS + mf * (16 * 80) + ks * 32);
#pragma unroll
            for (int nf2 = 0; nf2 < 4; nf2++)
                LDSM_X4(b[ks][nf2][0], b[ks][nf2][1], b[ks][nf2][2], b[ks][nf2][3],
                        bS + nf2 * (16 * 80) + ks * 32);
        }
#pragma unroll
        for (int ks = 0; ks < 2; ks++)
#pragma unroll
            for (int mf = 0; mf < 2; mf++)
#pragma unroll
                for (int nf2 = 0; nf2 < 4; nf2++) {
                    MMA16816(c_[mf][nf2 * 2][0], c_[mf][nf2 * 2][1],
                             c_[mf][nf2 * 2][2], c_[mf][nf2 * 2][3],
                             a[ks][mf][0], a[ks][mf][1], a[ks][mf][2], a[ks][mf][3],
                             b[ks][nf2][0], b[ks][nf2][1]);
                    MMA16816(c_[mf][nf2 * 2 + 1][0], c_[mf][nf2 * 2 + 1][1],
                             c_[mf][nf2 * 2 + 1][2], c_[mf][nf2 * 2 + 1][3],
                             a[ks][mf][0], a[ks][mf][1], a[ks][mf][2], a[ks][mf][3],
                             b[ks][nf2][2], b[ks][nf2][3]);
                }
    };

#pragma unroll 1
    for (int cc = 0; cc < NCHUNK; cc += 4) {
        step(cc + 0, 0, 3);
        step(cc + 1, 1, 0);
        step(cc + 2, 2, 1);
        step(cc + 3, 3, 2);
    }

    // Epilogue: threshold filter + candidate append (no sim store)
    const int rBase = mBase + wm * 32 + (lane >> 2);
    const int cBase = nBase + wn * 64 + (lane & 3) * 2;
#pragma unroll
    for (int mf = 0; mf < 2; mf++) {
        const int r0 = rBase + mf * 16;
#pragma unroll
        for (int nf = 0; nf < 8; nf++) {
            const int col = cBase + nf * 8;
            cand_append(r0,     col,     c_[mf][nf][0]);
            cand_append(r0,     col + 1, c_[mf][nf][1]);
            cand_append(r0 + 8, col,     c_[mf][nf][2]);
            cand_append(r0 + 8, col + 1, c_[mf][nf][3]);
        }
    }
}

// ---------------------------------------------------------------------------
// Kernel 3: per-row top-200 + voting from the candidate lists (~615/row).
// Exact brute-force fp32 fallback (recompute from raw inputs + histogram
// select) if a row's count falls outside [TOPK, CCAP] — exact on ANY input.
// ---------------------------------------------------------------------------
__device__ __forceinline__ int sim_bin(float v)
{
    int b = (int)((v + 1.0f) * 2048.0f);
    return min(4095, max(0, b));
}

__global__ __launch_bounds__(256) void knn_select_kernel(const float* __restrict__ feats,
                                                         const float* __restrict__ qf,
                                                         const int* __restrict__ qlabels,
                                                         const int* __restrict__ labels)
{
    __shared__ float    cval[CCAP];
    __shared__ int      cidx[CCAP];
    __shared__ float    score[NCLS];
    __shared__ unsigned hist[4096];    // fallback only
    __shared__ float    frow[DIM];     // fallback only
    __shared__ unsigned s_cnt;
    __shared__ int      s_tbin;

    const int tid = threadIdx.x;
    const int row = blockIdx.x;

    for (int i = tid; i < NCLS; i += 256) score[i] = 0.0f;
    __syncthreads();

    int cnt = g_ccnt[row];

    if (cnt >= TOPK && cnt <= CCAP) {
        // ---- Fast path: load candidate list ----
        const float* gv = g_cval + (size_t)row * CCAP;
        const int*   gi = g_cidx + (size_t)row * CCAP;
        for (int i = tid; i < CCAP; i += 256) {
            if (i < cnt) { cval[i] = gv[i]; cidx[i] = gi[i]; }
            else         { cval[i] = -2.0f; cidx[i] = 0x7FFFFFFF; }
        }
        __syncthreads();
    } else {
        // ---- Exact fallback: brute-force fp32 recompute of this row ----
        for (int i = tid; i < DIM; i += 256) frow[i] = feats[row * DIM + i];
        for (int b = tid; b < 4096; b += 256) hist[b] = 0;
        if (tid == 0) s_cnt = 0;
        __syncthreads();
        for (int k = tid; k < KQ; k += 256) {
            const float* q = qf + (size_t)k * DIM;
            float d = 0.f;
            for (int j = 0; j < DIM; j++) d += frow[j] * q[j];
            atomicAdd(&hist[sim_bin(d)], 1u);
        }
        __syncthreads();
        if (tid == 0) {
            unsigned cum = 0; int tb = 0;
            for (int b = 4095; b >= 0; b--) {
                if (cum + hist[b] >= (unsigned)TOPK) { tb = b; break; }
                cum += hist[b];
            }
            s_tbin = tb;
        }
        __syncthreads();
        const int tb = s_tbin;
        for (int k = tid; k < KQ; k += 256) {
            const float* q = qf + (size_t)k * DIM;
            float d = 0.f;
            for (int j = 0; j < DIM; j++) d += frow[j] * q[j];
            if (sim_bin(d) >= tb) {
                unsigned pos = atomicAdd(&s_cnt, 1u);
                if (pos < (unsigned)CCAP) { cval[pos] = d; cidx[pos] = k; }
            }
        }
        __syncthreads();
        const int m = (int)min(s_cnt, (unsigned)CCAP);
        for (int i = tid; i < CCAP; i += 256)
            if (i >= m) { cval[i] = -2.0f; cidx[i] = 0x7FFFFFFF; }
        __syncthreads();
    }

    // Bitonic sort 1024: descending by value, ascending by index on ties
    for (int k = 2; k <= CCAP; k <<= 1) {
        for (int j = k >> 1; j > 0; j >>= 1) {
            for (int t = tid; t < CCAP; t += 256) {
                const int p = t ^ j;
                if (p > t) {
                    float v1 = cval[t], v2 = cval[p];
                    int i1 = cidx[t], i2 = cidx[p];
                    bool firstGreater = (v1 > v2) || (v1 == v2 && i1 < i2);
                    bool up = ((t & k) == 0);
                    if (up != firstGreater) {
                        cval[t] = v2; cval[p] = v1;
                        cidx[t] = i2; cidx[p] = i1;
                    }
                }
            }
            __syncthreads();
        }
    }

    // Vote: exact top-200 weights scattered into per-class scores
    if (tid < TOPK) {
        float w = expf(cval[tid] * (1.0f / 0.07f));
        atomicAdd(&score[qlabels[cidx[tid]]], w);
    }
    __syncthreads();

    // Argmax over classes (lowest class index on ties)
    float best = -1.0f;
    int bc = 0;
#pragma unroll
    for (int rep = 0; rep < 4; rep++) {
        const int c = tid + rep * 256;
        if (c < NCLS) {
            float sc = score[c];
            if (sc > best) { best = sc; bc = c; }
        }
    }
    __syncthreads();
    cval[tid] = best; cidx[tid] = bc;
    __syncthreads();
    for (int off = 128; off > 0; off >>= 1) {
        if (tid < off) {
            float v2 = cval[tid + off]; int c2 = cidx[tid + off];
            if (v2 > cval[tid] || (v2 == cval[tid] && c2 < cidx[tid])) {
                cval[tid] = v2; cidx[tid] = c2;
            }
        }
        __syncthreads();
    }
    if (tid == 0 && cidx[0] == labels[row]) atomicAdd(&g_correct, 1);
}

__global__ void finalize_kernel(float* __restrict__ out)
{
    out[0] = (float)g_correct * (1.0f / 1024.0f);
}

// ---------------------------------------------------------------------------
extern "C" void kernel_launch(void* const* d_in, const int* in_sizes, int n_in,
                              void* d_out, int out_size)
{
    const float* feats   = (const float*)d_in[0];
    const float* qf      = (const float*)d_in[1];
    const int*   labels  = (const int*)d_in[2];
    const int*   qlabels = (const int*)d_in[3];
    const int*   qptr    = (const int*)d_in[4];
    float* out = (float*)d_out;

    cudaFuncSetAttribute(gemm_tc_kernel, cudaFuncAttributeMaxDynamicSharedMemorySize, GEMM_SMEM);

    conv_a_kernel<<<(NQ * DIM / 4) / 256, 256>>>(feats);

    const long long total = (long long)NF4 + KQ + 1;
    copy_conv_b_kernel<<<(int)((total + 255) / 256), 256>>>(feats, qf, labels, qlabels, qptr, out);

    gemm_tc_kernel<<<dim3(8, 512), 256, GEMM_SMEM>>>();
    knn_select_kernel<<<NQ, 256>>>(feats, qf, qlabels, labels);
    finalize_kernel<<<1, 1>>>(out);
}